// round 4
// baseline (speedup 1.0000x reference)
#include <cuda_runtime.h>

// TemporalSpike: RLeaky SNN recurrence, nibble-LUT version.
//   rec   = spk_prev @ W^T + b_lin   (spk binary; warp-uniform ballot mask ->
//                                     8 nibble lookups in a 16KB smem table)
//   mem   = 0.9*mem + x_t + rec - spk_prev
//   spk   = (mem > 1.0)
// Shapes: x (16,128,512,32); W (32,32); b_lin (32).
// Out: spikes (16,128,512,32) then mems, concatenated.

#define BB 16
#define TT 128
#define NN 512
#define FF 32
#define ROWS (BB * NN)          // 8192 independent recurrences
#define WPB 8                   // warps per block
#define TSTRIDE (NN * FF)       // 16384 floats between consecutive t

// tab[p][v][g]: p = nibble position (0..7), v = nibble value (0..15), g = lane.
// Entry = sum of W[g][4p+j] over set bits j of v; bias folded into p==0.
#define TAB_ELEMS (8 * 16 * 32)

__global__ __launch_bounds__(WPB * 32, 6)
void temporal_spike_kernel(const float* __restrict__ x,
                           const float* __restrict__ W,
                           const float* __restrict__ b_lin,
                           float* __restrict__ out)
{
    __shared__ float tab[TAB_ELEMS];   // 16 KB

    const int lane = threadIdx.x & 31;

    // Build the LUT: 4096 entries, 256 threads -> 16 each.
    for (int e = threadIdx.x; e < TAB_ELEMS; e += WPB * 32) {
        const int g = e & 31;
        const int v = (e >> 5) & 15;
        const int p = e >> 9;
        float s = (p == 0) ? b_lin[g] : 0.0f;
        const float* wr = W + g * FF + 4 * p;
        #pragma unroll
        for (int j = 0; j < 4; j++)
            if (v & (1 << j)) s += wr[j];
        tab[e] = s;
    }
    __syncthreads();

    const int warp = blockIdx.x * WPB + (threadIdx.x >> 5);
    const int b = warp >> 9;        // / NN
    const int n = warp & (NN - 1);

    const int base = (b * TT * NN + n) * FF + lane;   // t=0 element for this lane
    const float* xp = x + base;
    float* sp = out + base;                            // spikes
    float* mp = sp + (size_t)BB * TT * NN * FF;        // mems (second half)

    float mem = 0.0f;
    float spk = 0.0f;
    unsigned mask = 0u;

    // Prefetch pipeline for x (independent of the recurrence), depth 4.
    float xbuf[4];
    #pragma unroll
    for (int i = 0; i < 4; i++) xbuf[i] = xp[i * TSTRIDE];

    #pragma unroll 4
    for (int t = 0; t < TT; t++) {
        const float xv = xbuf[t & 3];
        if (t + 4 < TT) xbuf[t & 3] = xp[(t + 4) * TSTRIDE];

        // rec = sum of 8 nibble-table entries (mask is warp-uniform, so the
        // v index is identical across lanes; lane-major layout -> no conflicts).
        float r0, r1, r2, r3;
        r0 = tab[0 * 512 + (( mask        ) & 15) * 32 + lane];
        r1 = tab[1 * 512 + (( mask >>  4  ) & 15) * 32 + lane];
        r2 = tab[2 * 512 + (( mask >>  8  ) & 15) * 32 + lane];
        r3 = tab[3 * 512 + (( mask >> 12  ) & 15) * 32 + lane];
        r0 += tab[4 * 512 + (( mask >> 16 ) & 15) * 32 + lane];
        r1 += tab[5 * 512 + (( mask >> 20 ) & 15) * 32 + lane];
        r2 += tab[6 * 512 + (( mask >> 24 ) & 15) * 32 + lane];
        r3 += tab[7 * 512 + (( mask >> 28 )     ) * 32 + lane];
        const float rec = (r0 + r1) + (r2 + r3);

        mem = fmaf(0.9f, mem, xv + rec - spk);   // THRESH=1 -> subtract spk
        const bool fire = (mem > 1.0f);
        spk = fire ? 1.0f : 0.0f;
        mask = __ballot_sync(0xffffffffu, fire);

        sp[t * TSTRIDE] = spk;
        mp[t * TSTRIDE] = mem;
    }
}

extern "C" void kernel_launch(void* const* d_in, const int* in_sizes, int n_in,
                              void* d_out, int out_size)
{
    const float* x     = (const float*)d_in[0];
    const float* W     = (const float*)d_in[1];
    const float* b_lin = (const float*)d_in[2];
    float* out = (float*)d_out;

    dim3 grid(ROWS / WPB);     // 1024
    dim3 block(WPB * 32);      // 256
    temporal_spike_kernel<<<grid, block>>>(x, W, b_lin, out);
}

// round 5
// speedup vs baseline: 1.0026x; 1.0026x over previous
#include <cuda_runtime.h>

// TemporalSpike: RLeaky SNN recurrence, nibble-LUT version.
//   rec   = spk_prev @ W^T + b_lin   (spk binary; warp-uniform ballot mask ->
//                                     8 nibble lookups in a 16KB smem table)
//   mem   = 0.9*mem + x_t + rec - spk_prev
//   spk   = (mem > 1.0)
// Shapes: x (16,128,512,32); W (32,32); b_lin (32).
// Out: spikes (16,128,512,32) then mems, concatenated.
//
// R4 change: __launch_bounds__(256,8) -> 2048 thr/SM (occ ~100%), and the
// whole 1024-block grid fits in ONE wave (8*148=1184 blocks capacity):
// no wave tail, 8 warps/SMSP to hide the ~95-cycle per-step serial chain.

#define BB 16
#define TT 128
#define NN 512
#define FF 32
#define ROWS (BB * NN)          // 8192 independent recurrences
#define WPB 8                   // warps per block
#define TSTRIDE (NN * FF)       // 16384 floats between consecutive t

// tab[p][v][g]: p = nibble position (0..7), v = nibble value (0..15), g = lane.
// Entry = sum of W[g][4p+j] over set bits j of v; bias folded into p==0.
#define TAB_ELEMS (8 * 16 * 32)

__global__ __launch_bounds__(WPB * 32, 8)
void temporal_spike_kernel(const float* __restrict__ x,
                           const float* __restrict__ W,
                           const float* __restrict__ b_lin,
                           float* __restrict__ out)
{
    __shared__ float tab[TAB_ELEMS];   // 16 KB

    const int lane = threadIdx.x & 31;

    // Build the LUT: 4096 entries, 256 threads -> 16 each.
    for (int e = threadIdx.x; e < TAB_ELEMS; e += WPB * 32) {
        const int g = e & 31;
        const int v = (e >> 5) & 15;
        const int p = e >> 9;
        float s = (p == 0) ? b_lin[g] : 0.0f;
        const float* wr = W + g * FF + 4 * p;
        #pragma unroll
        for (int j = 0; j < 4; j++)
            if (v & (1 << j)) s += wr[j];
        tab[e] = s;
    }
    __syncthreads();

    const int warp = blockIdx.x * WPB + (threadIdx.x >> 5);
    const int b = warp >> 9;        // / NN
    const int n = warp & (NN - 1);

    const int base = (b * TT * NN + n) * FF + lane;   // t=0 element for this lane
    const float* xp = x + base;
    float* sp = out + base;                            // spikes
    float* mp = sp + (size_t)BB * TT * NN * FF;        // mems (second half)

    float mem = 0.0f;
    float spk = 0.0f;
    unsigned mask = 0u;

    // Prefetch pipeline for x (independent of the recurrence), depth 4.
    float xbuf[4];
    #pragma unroll
    for (int i = 0; i < 4; i++) xbuf[i] = xp[i * TSTRIDE];

    #pragma unroll 4
    for (int t = 0; t < TT; t++) {
        const float xv = xbuf[t & 3];
        if (t + 4 < TT) xbuf[t & 3] = xp[(t + 4) * TSTRIDE];

        // rec = sum of 8 nibble-table entries (mask is warp-uniform, so the
        // v index is identical across lanes; lane-major layout -> no conflicts).
        float r0, r1, r2, r3;
        r0 = tab[0 * 512 + (( mask        ) & 15) * 32 + lane];
        r1 = tab[1 * 512 + (( mask >>  4  ) & 15) * 32 + lane];
        r2 = tab[2 * 512 + (( mask >>  8  ) & 15) * 32 + lane];
        r3 = tab[3 * 512 + (( mask >> 12  ) & 15) * 32 + lane];
        r0 += tab[4 * 512 + (( mask >> 16 ) & 15) * 32 + lane];
        r1 += tab[5 * 512 + (( mask >> 20 ) & 15) * 32 + lane];
        r2 += tab[6 * 512 + (( mask >> 24 ) & 15) * 32 + lane];
        r3 += tab[7 * 512 + (( mask >> 28 )     ) * 32 + lane];
        const float rec = (r0 + r1) + (r2 + r3);

        mem = fmaf(0.9f, mem, xv + rec - spk);   // THRESH=1 -> subtract spk
        const bool fire = (mem > 1.0f);
        spk = fire ? 1.0f : 0.0f;
        mask = __ballot_sync(0xffffffffu, fire);

        sp[t * TSTRIDE] = spk;
        mp[t * TSTRIDE] = mem;
    }
}

extern "C" void kernel_launch(void* const* d_in, const int* in_sizes, int n_in,
                              void* d_out, int out_size)
{
    const float* x     = (const float*)d_in[0];
    const float* W     = (const float*)d_in[1];
    const float* b_lin = (const float*)d_in[2];
    float* out = (float*)d_out;

    dim3 grid(ROWS / WPB);     // 1024
    dim3 block(WPB * 32);      // 256
    temporal_spike_kernel<<<grid, block>>>(x, W, b_lin, out);
}